// round 8
// baseline (speedup 1.0000x reference)
#include <cuda_runtime.h>
#include <cuda_bf16.h>
#include <cstdint>

#define NB 8
#define PP 256
#define CC 128
#define US 132          // fp32 smem pad stride (proj kernel)
#define HS 136          // bf16 smem pad stride in halves (272B): conflict-free ldmatrix

// ---- scratch (no allocation allowed) --------------------------------------
__device__ __align__(16) float g_M[CC*CC];     // Wp2 @ W1
__device__ __align__(16) float g_Wq1[CC*CC];   // Wq @ W1
__device__ __align__(16) float g_Wk1[CC*CC];   // Wk @ W1
__device__ __align__(16) float g_c0[CC];       // b1 + bp2 @ W1
__device__ __align__(16) float g_v[NB*PP*CC];
__device__ __align__(16) float g_qW1[NB*PP*CC];
__device__ __align__(16) float g_kW1[NB*PP*CC];
// Mt (=M^T) split bf16 hi/lo, n-major rows: row d (out dim), 128 k cols, packed pairs
__device__ __align__(16) unsigned g_Bhi[CC*64];
__device__ __align__(16) unsigned g_Blo[CC*64];

// ---- helpers --------------------------------------------------------------
__device__ __forceinline__ uint32_t smem_u32(const void* p) {
    uint32_t r;
    asm("{ .reg .u64 t; cvta.to.shared.u64 t, %1; cvt.u32.u64 %0, t; }" : "=r"(r) : "l"(p));
    return r;
}
__device__ __forceinline__ void ldsm_x4(uint32_t* r, uint32_t addr) {
    asm volatile("ldmatrix.sync.aligned.m8n8.x4.shared.b16 {%0,%1,%2,%3}, [%4];"
                 : "=r"(r[0]), "=r"(r[1]), "=r"(r[2]), "=r"(r[3]) : "r"(addr));
}
__device__ __forceinline__ void mma16816(float* d, const uint32_t* a, uint32_t b0, uint32_t b1) {
    asm volatile("mma.sync.aligned.m16n8k16.row.col.f32.bf16.bf16.f32 "
                 "{%0,%1,%2,%3}, {%4,%5,%6,%7}, {%8,%9}, {%0,%1,%2,%3};"
                 : "+f"(d[0]), "+f"(d[1]), "+f"(d[2]), "+f"(d[3])
                 : "r"(a[0]), "r"(a[1]), "r"(a[2]), "r"(a[3]), "r"(b0), "r"(b1));
}
__device__ __forceinline__ unsigned pack_hi(float x, float y) {
    __nv_bfloat16 h0 = __float2bfloat16_rn(x), h1 = __float2bfloat16_rn(y);
    return ((unsigned)__bfloat16_as_ushort(h1) << 16) | __bfloat16_as_ushort(h0);
}
__device__ __forceinline__ unsigned pack_lo(float x, float y) {
    __nv_bfloat16 h0 = __float2bfloat16_rn(x), h1 = __float2bfloat16_rn(y);
    __nv_bfloat16 l0 = __float2bfloat16_rn(x - __bfloat162float(h0));
    __nv_bfloat16 l1 = __float2bfloat16_rn(y - __bfloat162float(h1));
    return ((unsigned)__bfloat16_as_ushort(l1) << 16) | __bfloat16_as_ushort(l0);
}

// ---------------------------------------------------------------------------
// prep1: parallel weight-fold GEMMs (M, Wq1, Wk1, c0). grid (8,3), W1 in smem.
// ---------------------------------------------------------------------------
__global__ __launch_bounds__(256)
void prep1(const float* __restrict__ Wq, const float* __restrict__ Wk,
           const float* __restrict__ Wp2, const float* __restrict__ W1,
           const float* __restrict__ b1, const float* __restrict__ bp2) {
    extern __shared__ float sm[];
    float* W1s = sm;           // 16384 floats
    float* Ash = sm + CC*CC;   // 16*128
    const float* A = (blockIdx.y == 0) ? Wp2 : ((blockIdx.y == 1) ? Wq : Wk);
    float* O       = (blockIdx.y == 0) ? g_M : ((blockIdx.y == 1) ? g_Wq1 : g_Wk1);
    int r0 = blockIdx.x * 16;
    int tid = threadIdx.x;
    for (int i = tid; i < CC*CC/4; i += 256) ((float4*)W1s)[i] = ((const float4*)W1)[i];
    for (int i = tid; i < 16*CC/4; i += 256) ((float4*)Ash)[i] = ((const float4*)(A + r0*CC))[i];
    __syncthreads();
    int d = tid & 127, r2 = tid >> 7;
    #pragma unroll
    for (int rr = 0; rr < 8; rr++) {
        int r = r2*8 + rr;
        float s = 0.f;
        #pragma unroll 8
        for (int e = 0; e < CC; e++) s = fmaf(Ash[r*CC + e], W1s[e*CC + d], s);
        O[(r0 + r)*CC + d] = s;
    }
    if (blockIdx.x == 0 && blockIdx.y == 0 && tid < CC) {
        float s = b1[tid];
        for (int e = 0; e < CC; e++) s = fmaf(bp2[e], W1s[e*CC + tid], s);
        g_c0[tid] = s;
    }
}

// ---------------------------------------------------------------------------
// prep2: build Mt (=M^T) bf16 hi/lo, plain n-major (row=d, 64 packed k-pairs)
// ---------------------------------------------------------------------------
__global__ void prep2() {
    int i = blockIdx.x * 256 + threadIdx.x;      // 0..8191
    int d = i >> 6, pc = i & 63, c = pc * 2;
    float m0 = g_M[c*CC + d], m1 = g_M[(c+1)*CC + d];   // Mt[d][c], Mt[d][c+1]
    g_Bhi[d*64 + pc] = pack_hi(m0, m1);
    g_Blo[d*64 + pc] = pack_lo(m0, m1);
}

// ---------------------------------------------------------------------------
// proj: v = x@Wv, qW1 = x@Wq1, kW1 = x@Wk1  (fp32 SIMT)
// ---------------------------------------------------------------------------
__global__ __launch_bounds__(256, 2)
void proj_kernel(const float* __restrict__ x, const float* __restrict__ Wv) {
    extern __shared__ float sm[];
    float* Wsh = sm;
    float* Xsh = sm + CC*CC;
    int which = blockIdx.y;
    const float* W = (which == 0) ? Wv  : ((which == 1) ? g_Wq1 : g_Wk1);
    float*       O = (which == 0) ? g_v : ((which == 1) ? g_qW1 : g_kW1);
    int row0 = blockIdx.x * 64;
    int tid = threadIdx.x;
    for (int i = tid; i < CC*CC/4; i += 256) ((float4*)Wsh)[i] = ((const float4*)W)[i];
    for (int i = tid; i < 64*CC; i += 256) {
        int r = i >> 7, c = i & 127;
        Xsh[r*US + c] = x[(row0 + r)*CC + c];
    }
    __syncthreads();
    int tx = tid & 15, ty = tid >> 4;
    float acc[4][8];
    #pragma unroll
    for (int i = 0; i < 4; i++)
        #pragma unroll
        for (int j = 0; j < 8; j++) acc[i][j] = 0.f;
    #pragma unroll 4
    for (int c = 0; c < CC; c++) {
        float4 m0 = *(const float4*)&Wsh[c*CC + (tx << 3)];
        float4 m1 = *(const float4*)&Wsh[c*CC + (tx << 3) + 4];
        float m[8] = {m0.x, m0.y, m0.z, m0.w, m1.x, m1.y, m1.z, m1.w};
        float u[4];
        #pragma unroll
        for (int i = 0; i < 4; i++) u[i] = Xsh[(ty*4 + i)*US + c];
        #pragma unroll
        for (int i = 0; i < 4; i++)
            #pragma unroll
            for (int j = 0; j < 8; j++) acc[i][j] += u[i] * m[j];
    }
    #pragma unroll
    for (int i = 0; i < 4; i++) {
        float4* o4 = (float4*)&O[(row0 + ty*4 + i)*CC + (tx << 3)];
        o4[0] = make_float4(acc[i][0], acc[i][1], acc[i][2], acc[i][3]);
        o4[1] = make_float4(acc[i][4], acc[i][5], acc[i][6], acc[i][7]);
    }
}

// ---------------------------------------------------------------------------
// main: per (n,a) block, 512 threads / 16 warps = 4 m-groups x 4 c-quarters.
// Each warp: m64 x n32 x k128 in ONE pass (B read once per warp -> half the
// smem crossbar traffic of R6). Merged 3-term split-precision bf16 mma.sync.
// Partial logits per c-quarter summed in smem, softmax, att@v, residual.
// ---------------------------------------------------------------------------
__global__ __launch_bounds__(512, 1)
void main_kernel(const float* __restrict__ x, const float* __restrict__ pos,
                 const float* __restrict__ W2, const float* __restrict__ Wp1,
                 const float* __restrict__ bp1, float* __restrict__ out) {
    extern __shared__ __align__(16) char dyn[];
    __shared__ float kcsh[CC], W2sh[CC], wpa[CC], wpb[CC], bpsh[CC];
    __shared__ float logits[PP], red[2*PP], pos_s[2*PP];
    __shared__ float lp[4][PP];          // per-c-quarter partial logits

    const int blk = blockIdx.x;
    const int n = blk >> 8, a = blk & 255;
    const int tid = threadIdx.x;
    const int lane = tid & 31, w = tid >> 5;

    unsigned* Uhi = (unsigned*)dyn;                  // packed bf16 pairs
    unsigned* Ulo = (unsigned*)(dyn + 69632);
    unsigned* Bhi = (unsigned*)(dyn + 139264);
    unsigned* Blo = (unsigned*)(dyn + 174080);
    const uint32_t UhiA = smem_u32(dyn);
    const uint32_t UloA = UhiA + 69632;
    const uint32_t BhiA = UhiA + 139264;
    const uint32_t BloA = UhiA + 174080;

    // stage small vectors, B tiles, pos rows
    if (tid < CC) {
        kcsh[tid] = g_c0[tid] - g_kW1[(n*PP + a)*CC + tid];
        W2sh[tid] = W2[tid];
        wpa[tid]  = Wp1[tid];
        wpb[tid]  = Wp1[CC + tid];
        bpsh[tid] = bp1[tid];
    }
    for (int i = tid; i < CC*64; i += 512) {      // B: insert pad stride (HS/2=68 uints)
        int r = i >> 6, j = i & 63;
        Bhi[r*68 + j] = g_Bhi[i];
        Blo[r*68 + j] = g_Blo[i];
    }
    for (int i = tid; i < 2*PP; i += 512)
        pos_s[i] = pos[((n*PP + a)*PP)*2 + i];
    __syncthreads();

    // build U = relu(pos@Wp1+bp1) -> bf16 hi/lo, k-major padded rows
    for (int i = tid; i < PP*64; i += 512) {
        int r = i >> 6, j = i & 63, c = j*2;
        float px = pos_s[r*2], py = pos_s[r*2 + 1];
        float u0 = fmaxf(fmaf(px, wpa[c],   fmaf(py, wpb[c],   bpsh[c]  )), 0.f);
        float u1 = fmaxf(fmaf(px, wpa[c+1], fmaf(py, wpb[c+1], bpsh[c+1])), 0.f);
        Uhi[r*68 + j] = pack_hi(u0, u1);
        Ulo[r*68 + j] = pack_lo(u0, u1);
    }
    __syncthreads();

    // ---- warp GEMM: warp = (mt, ci); m64 x n32 x k128, single pass ----
    const int ci = w & 3;          // c-quarter: cols [ci*32, ci*32+32)
    const int mt = w >> 2;         // m-group: rows [mt*64, mt*64+64)
    const int n0 = ci * 32;
    const int m0 = mt * 64;

    const int arow = ((lane >> 3) & 1) * 8 + (lane & 7);  // ldmatrix x4 lane row
    const int acol = (lane >> 4) * 8;
    const int brow = lane & 15;
    const int bcol = (lane >> 4) * 8;

    const uint32_t boff0 = (uint32_t)(((n0      + brow) * HS) + bcol) * 2u;
    const uint32_t boff1 = (uint32_t)(((n0 + 16 + brow) * HS) + bcol) * 2u;
    const uint32_t aoffb = (uint32_t)(((m0 + arow) * HS) + acol) * 2u;
    const int qcol = n0 + (lane & 3)*2;

    float acc[4][4][4];            // [m-subtile][nt][elem]
    #pragma unroll
    for (int ms = 0; ms < 4; ms++)
        #pragma unroll
        for (int nt = 0; nt < 4; nt++)
            #pragma unroll
            for (int e = 0; e < 4; e++) acc[ms][nt][e] = 0.f;

    #pragma unroll
    for (int kt = 0; kt < 8; kt++) {
        const uint32_t ka = (uint32_t)(kt * 16) * 2u;
        uint32_t bh0[4], bl0[4], bh1[4], bl1[4];
        ldsm_x4(bh0, BhiA + boff0 + ka);
        ldsm_x4(bl0, BloA + boff0 + ka);
        ldsm_x4(bh1, BhiA + boff1 + ka);
        ldsm_x4(bl1, BloA + boff1 + ka);
        #pragma unroll
        for (int ms = 0; ms < 4; ms++) {
            const uint32_t ao = aoffb + (uint32_t)(ms * 16 * HS) * 2u + ka;
            uint32_t ah[4], al[4];
            ldsm_x4(ah, UhiA + ao);
            ldsm_x4(al, UloA + ao);
            #pragma unroll
            for (int sub = 0; sub < 2; sub++) {
                mma16816(acc[ms][sub],   ah, bh0[sub], bh0[2+sub]);
                mma16816(acc[ms][2+sub], ah, bh1[sub], bh1[2+sub]);
                mma16816(acc[ms][sub],   ah, bl0[sub], bl0[2+sub]);
                mma16816(acc[ms][2+sub], ah, bl1[sub], bl1[2+sub]);
                mma16816(acc[ms][sub],   al, bh0[sub], bh0[2+sub]);
                mma16816(acc[ms][2+sub], al, bh1[sub], bh1[2+sub]);
            }
        }
    }

    // fused epilogue: partial logits over this c-quarter for 64 rows
    #pragma unroll
    for (int ms = 0; ms < 4; ms++) {
        #pragma unroll
        for (int rh = 0; rh < 2; rh++) {
            int b = m0 + ms*16 + rh*8 + (lane >> 2);
            const float2* qp = (const float2*)(g_qW1 + (size_t)(n*PP + b)*CC + qcol);
            float rp = 0.f;
            #pragma unroll
            for (int nt = 0; nt < 4; nt++) {
                float2 q2 = __ldg(&qp[nt*4]);
                int c = n0 + nt*8 + (lane & 3)*2;
                float h0 = acc[ms][nt][rh*2 + 0] + q2.x + kcsh[c];
                float h1 = acc[ms][nt][rh*2 + 1] + q2.y + kcsh[c + 1];
                rp = fmaf(fmaxf(h0, 0.f), W2sh[c],
                     fmaf(fmaxf(h1, 0.f), W2sh[c + 1], rp));
            }
            rp += __shfl_xor_sync(0xffffffffu, rp, 1);
            rp += __shfl_xor_sync(0xffffffffu, rp, 2);
            if ((lane & 3) == 0) lp[ci][b] = rp;
        }
    }
    __syncthreads();

    // combine c-quarter partials -> logits
    if (tid < PP)
        logits[tid] = (lp[0][tid] + lp[1][tid]) + (lp[2][tid] + lp[3][tid]);
    __syncthreads();

    // softmax over b (256 entries, first 256 threads active in reductions)
    float lv = (tid < PP) ? logits[tid] : 0.f;
    if (tid < PP) red[tid] = lv;
    __syncthreads();
    #pragma unroll
    for (int s = 128; s > 0; s >>= 1) {
        if (tid < s) red[tid] = fmaxf(red[tid], red[tid + s]);
        __syncthreads();
    }
    float mx = red[0];
    __syncthreads();
    float ev = expf(lv - mx);
    if (tid < PP) red[tid] = ev;
    __syncthreads();
    #pragma unroll
    for (int s = 128; s > 0; s >>= 1) {
        if (tid < s) red[tid] += red[tid + s];
        __syncthreads();
    }
    float inv = 1.0f / red[0];
    __syncthreads();
    if (tid < PP) logits[tid] = ev * inv;
    __syncthreads();

    // out[n,a,:] = x[n,a,:] + att @ v[n]   (4-way split of the b-sum)
    {
        int d = tid & 127, h = tid >> 7;       // h in 0..3
        const float* vb = &g_v[(size_t)(n*PP + h*64)*CC + d];
        float s0 = 0.f, s1 = 0.f;
        #pragma unroll 4
        for (int b = 0; b < 64; b += 2) {
            s0 = fmaf(logits[h*64 + b    ], vb[(size_t)b*CC],     s0);
            s1 = fmaf(logits[h*64 + b + 1], vb[(size_t)(b+1)*CC], s1);
        }
        red[tid] = s0 + s1;
    }
    __syncthreads();
    if (tid < CC) {
        size_t o = (size_t)(n*PP + a)*CC + tid;
        out[o] = x[o] + ((red[tid] + red[tid + 128]) + (red[tid + 256] + red[tid + 384]));
    }
}

// ---------------------------------------------------------------------------
extern "C" void kernel_launch(void* const* d_in, const int* in_sizes, int n_in,
                              void* d_out, int out_size) {
    const float* x   = (const float*)d_in[0];
    const float* pos = (const float*)d_in[1];
    const float* Wq  = (const float*)d_in[2];
    const float* Wk  = (const float*)d_in[3];
    const float* Wv  = (const float*)d_in[4];
    const float* W1  = (const float*)d_in[5];
    const float* b1  = (const float*)d_in[6];
    const float* W2  = (const float*)d_in[7];
    // d_in[8] = b2: cancelled by softmax
    const float* Wp1 = (const float*)d_in[9];
    const float* bp1 = (const float*)d_in[10];
    const float* Wp2 = (const float*)d_in[11];
    const float* bp2 = (const float*)d_in[12];
    float* out = (float*)d_out;

    const int smem_prep = (CC*CC + 16*CC) * 4;   // 73728
    const int smem_proj = (CC*CC + 64*US) * 4;   // 99328
    const int smem_main = 208896;                // Uhi/Ulo/Bhi/Blo padded bf16
    cudaFuncSetAttribute(prep1,       cudaFuncAttributeMaxDynamicSharedMemorySize, smem_prep);
    cudaFuncSetAttribute(proj_kernel, cudaFuncAttributeMaxDynamicSharedMemorySize, smem_proj);
    cudaFuncSetAttribute(main_kernel, cudaFuncAttributeMaxDynamicSharedMemorySize, smem_main);

    prep1<<<dim3(8, 3), 256, smem_prep>>>(Wq, Wk, Wp2, W1, b1, bp2);
    prep2<<<32, 256>>>();
    proj_kernel<<<dim3(NB*PP/64, 3), 256, smem_proj>>>(x, Wv);
    main_kernel<<<NB*PP, 512, smem_main>>>(x, pos, W2, Wp1, bp1, out);
}

// round 9
// speedup vs baseline: 1.2824x; 1.2824x over previous
#include <cuda_runtime.h>
#include <cuda_bf16.h>
#include <cstdint>

#define NB 8
#define PP 256
#define CC 128
#define US 132          // fp32 smem pad stride (proj kernel)
#define HS 136          // bf16 smem pad stride in halves (272B): conflict-free ldmatrix

// ---- scratch (no allocation allowed) --------------------------------------
__device__ __align__(16) float g_M[CC*CC];     // Wp2 @ W1
__device__ __align__(16) float g_Wq1[CC*CC];   // Wq @ W1
__device__ __align__(16) float g_Wk1[CC*CC];   // Wk @ W1
__device__ __align__(16) float g_c0[CC];       // b1 + bp2 @ W1
__device__ __align__(16) float g_v[NB*PP*CC];
__device__ __align__(16) float g_qW1[NB*PP*CC];
__device__ __align__(16) float g_kW1[NB*PP*CC];
// Mt (=M^T) split bf16 hi/lo, n-major rows: row d (out dim), 128 k cols, packed pairs
__device__ __align__(16) unsigned g_Bhi[CC*64];
__device__ __align__(16) unsigned g_Blo[CC*64];

// ---- helpers --------------------------------------------------------------
__device__ __forceinline__ uint32_t smem_u32(const void* p) {
    uint32_t r;
    asm("{ .reg .u64 t; cvta.to.shared.u64 t, %1; cvt.u32.u64 %0, t; }" : "=r"(r) : "l"(p));
    return r;
}
__device__ __forceinline__ void ldsm_x4(uint32_t* r, uint32_t addr) {
    asm volatile("ldmatrix.sync.aligned.m8n8.x4.shared.b16 {%0,%1,%2,%3}, [%4];"
                 : "=r"(r[0]), "=r"(r[1]), "=r"(r[2]), "=r"(r[3]) : "r"(addr));
}
__device__ __forceinline__ void mma16816(float* d, const uint32_t* a, uint32_t b0, uint32_t b1) {
    asm volatile("mma.sync.aligned.m16n8k16.row.col.f32.bf16.bf16.f32 "
                 "{%0,%1,%2,%3}, {%4,%5,%6,%7}, {%8,%9}, {%0,%1,%2,%3};"
                 : "+f"(d[0]), "+f"(d[1]), "+f"(d[2]), "+f"(d[3])
                 : "r"(a[0]), "r"(a[1]), "r"(a[2]), "r"(a[3]), "r"(b0), "r"(b1));
}
__device__ __forceinline__ unsigned pack_hi(float x, float y) {
    __nv_bfloat16 h0 = __float2bfloat16_rn(x), h1 = __float2bfloat16_rn(y);
    return ((unsigned)__bfloat16_as_ushort(h1) << 16) | __bfloat16_as_ushort(h0);
}
__device__ __forceinline__ unsigned pack_lo(float x, float y) {
    __nv_bfloat16 h0 = __float2bfloat16_rn(x), h1 = __float2bfloat16_rn(y);
    __nv_bfloat16 l0 = __float2bfloat16_rn(x - __bfloat162float(h0));
    __nv_bfloat16 l1 = __float2bfloat16_rn(y - __bfloat162float(h1));
    return ((unsigned)__bfloat16_as_ushort(l1) << 16) | __bfloat16_as_ushort(l0);
}

// ---------------------------------------------------------------------------
// prep1: parallel weight-fold GEMMs (M, Wq1, Wk1, c0). grid (8,3), W1 in smem.
// ---------------------------------------------------------------------------
__global__ __launch_bounds__(256)
void prep1(const float* __restrict__ Wq, const float* __restrict__ Wk,
           const float* __restrict__ Wp2, const float* __restrict__ W1,
           const float* __restrict__ b1, const float* __restrict__ bp2) {
    extern __shared__ float sm[];
    float* W1s = sm;           // 16384 floats
    float* Ash = sm + CC*CC;   // 16*128
    const float* A = (blockIdx.y == 0) ? Wp2 : ((blockIdx.y == 1) ? Wq : Wk);
    float* O       = (blockIdx.y == 0) ? g_M : ((blockIdx.y == 1) ? g_Wq1 : g_Wk1);
    int r0 = blockIdx.x * 16;
    int tid = threadIdx.x;
    for (int i = tid; i < CC*CC/4; i += 256) ((float4*)W1s)[i] = ((const float4*)W1)[i];
    for (int i = tid; i < 16*CC/4; i += 256) ((float4*)Ash)[i] = ((const float4*)(A + r0*CC))[i];
    __syncthreads();
    int d = tid & 127, r2 = tid >> 7;
    #pragma unroll
    for (int rr = 0; rr < 8; rr++) {
        int r = r2*8 + rr;
        float s = 0.f;
        #pragma unroll 8
        for (int e = 0; e < CC; e++) s = fmaf(Ash[r*CC + e], W1s[e*CC + d], s);
        O[(r0 + r)*CC + d] = s;
    }
    if (blockIdx.x == 0 && blockIdx.y == 0 && tid < CC) {
        float s = b1[tid];
        for (int e = 0; e < CC; e++) s = fmaf(bp2[e], W1s[e*CC + tid], s);
        g_c0[tid] = s;
    }
}

// ---------------------------------------------------------------------------
// prep2: build Mt (=M^T) bf16 hi/lo, plain n-major (row=d, 64 packed k-pairs)
// ---------------------------------------------------------------------------
__global__ void prep2() {
    int i = blockIdx.x * 256 + threadIdx.x;      // 0..8191
    int d = i >> 6, pc = i & 63, c = pc * 2;
    float m0 = g_M[c*CC + d], m1 = g_M[(c+1)*CC + d];   // Mt[d][c], Mt[d][c+1]
    g_Bhi[d*64 + pc] = pack_hi(m0, m1);
    g_Blo[d*64 + pc] = pack_lo(m0, m1);
}

// ---------------------------------------------------------------------------
// proj: v = x@Wv, qW1 = x@Wq1, kW1 = x@Wk1  (fp32 SIMT)
// ---------------------------------------------------------------------------
__global__ __launch_bounds__(256, 2)
void proj_kernel(const float* __restrict__ x, const float* __restrict__ Wv) {
    extern __shared__ float sm[];
    float* Wsh = sm;
    float* Xsh = sm + CC*CC;
    int which = blockIdx.y;
    const float* W = (which == 0) ? Wv  : ((which == 1) ? g_Wq1 : g_Wk1);
    float*       O = (which == 0) ? g_v : ((which == 1) ? g_qW1 : g_kW1);
    int row0 = blockIdx.x * 64;
    int tid = threadIdx.x;
    for (int i = tid; i < CC*CC/4; i += 256) ((float4*)Wsh)[i] = ((const float4*)W)[i];
    for (int i = tid; i < 64*CC; i += 256) {
        int r = i >> 7, c = i & 127;
        Xsh[r*US + c] = x[(row0 + r)*CC + c];
    }
    __syncthreads();
    int tx = tid & 15, ty = tid >> 4;
    float acc[4][8];
    #pragma unroll
    for (int i = 0; i < 4; i++)
        #pragma unroll
        for (int j = 0; j < 8; j++) acc[i][j] = 0.f;
    #pragma unroll 4
    for (int c = 0; c < CC; c++) {
        float4 m0 = *(const float4*)&Wsh[c*CC + (tx << 3)];
        float4 m1 = *(const float4*)&Wsh[c*CC + (tx << 3) + 4];
        float m[8] = {m0.x, m0.y, m0.z, m0.w, m1.x, m1.y, m1.z, m1.w};
        float u[4];
        #pragma unroll
        for (int i = 0; i < 4; i++) u[i] = Xsh[(ty*4 + i)*US + c];
        #pragma unroll
        for (int i = 0; i < 4; i++)
            #pragma unroll
            for (int j = 0; j < 8; j++) acc[i][j] += u[i] * m[j];
    }
    #pragma unroll
    for (int i = 0; i < 4; i++) {
        float4* o4 = (float4*)&O[(row0 + ty*4 + i)*CC + (tx << 3)];
        o4[0] = make_float4(acc[i][0], acc[i][1], acc[i][2], acc[i][3]);
        o4[1] = make_float4(acc[i][4], acc[i][5], acc[i][6], acc[i][7]);
    }
}

// ---------------------------------------------------------------------------
// main: per (n,a) block, 256 threads / 8 warps, TWO blocks per SM (smem
// ~102KB dyn). U built in 4 chunks of 64 rows; warp = (mh, ci): m32 x n32
// x k128 merged 3-term split-precision bf16 mma.sync per chunk. Cross-block
// phase overlap hides barrier/softmax serialization.
// ---------------------------------------------------------------------------
__global__ __launch_bounds__(256, 2)
void main_kernel(const float* __restrict__ x, const float* __restrict__ pos,
                 const float* __restrict__ W2, const float* __restrict__ Wp1,
                 const float* __restrict__ bp1, float* __restrict__ out) {
    extern __shared__ __align__(16) char dyn[];
    __shared__ float kcsh[CC], W2sh[CC], wpa[CC], wpb[CC], bpsh[CC];
    __shared__ float logits[PP], red[PP], lp[4][64], pos_c[128];

    const int blk = blockIdx.x;
    const int n = blk >> 8, a = blk & 255;
    const int tid = threadIdx.x;
    const int lane = tid & 31, w = tid >> 5;

    // dyn layout (bytes): Bhi 34816 | Blo 34816 | Uhi 17408 | Ulo 17408 = 104448
    unsigned* Bhi = (unsigned*)dyn;
    unsigned* Blo = (unsigned*)(dyn + 34816);
    unsigned* Uhi = (unsigned*)(dyn + 69632);
    unsigned* Ulo = (unsigned*)(dyn + 87040);
    const uint32_t BhiA = smem_u32(dyn);
    const uint32_t BloA = BhiA + 34816;
    const uint32_t UhiA = BhiA + 69632;
    const uint32_t UloA = BhiA + 87040;

    // stage small vectors + B tiles
    if (tid < CC) {
        kcsh[tid] = g_c0[tid] - g_kW1[(n*PP + a)*CC + tid];
        W2sh[tid] = W2[tid];
        wpa[tid]  = Wp1[tid];
        wpb[tid]  = Wp1[CC + tid];
        bpsh[tid] = bp1[tid];
    }
    for (int i = tid; i < CC*64; i += 256) {      // pad stride HS/2=68 uints
        int r = i >> 6, j = i & 63;
        Bhi[r*68 + j] = g_Bhi[i];
        Blo[r*68 + j] = g_Blo[i];
    }

    // warp roles
    const int ci = w & 3;          // c-quarter: cols [ci*32, +32)
    const int mh = w >> 2;         // m-half within 64-row chunk
    const int n0 = ci * 32;
    const int m0 = mh * 32;

    const int arow = ((lane >> 3) & 1) * 8 + (lane & 7);
    const int acol = (lane >> 4) * 8;
    const int brow = lane & 15;
    const int bcol = (lane >> 4) * 8;

    const uint32_t boff0 = (uint32_t)(((n0      + brow) * HS) + bcol) * 2u;
    const uint32_t boff1 = (uint32_t)(((n0 + 16 + brow) * HS) + bcol) * 2u;
    const uint32_t aoffb = (uint32_t)(((m0 + arow) * HS) + acol) * 2u;
    const int qcol = n0 + (lane & 3)*2;

    const float* posrow = pos + (size_t)((n*PP + a)*PP) * 2;

    #pragma unroll 1
    for (int chunk = 0; chunk < 4; chunk++) {
        // stage pos rows for this chunk (also serves as barrier after prior
        // chunk's lp-consumption / B-staging on first iteration)
        if (tid < 128) pos_c[tid] = posrow[chunk*128 + tid];
        __syncthreads();

        // build U chunk = relu(pos@Wp1+bp1) -> bf16 hi/lo
        for (int i = tid; i < 64*64; i += 256) {
            int r = i >> 6, j = i & 63, c = j*2;
            float px = pos_c[r*2], py = pos_c[r*2 + 1];
            float u0 = fmaxf(fmaf(px, wpa[c],   fmaf(py, wpb[c],   bpsh[c]  )), 0.f);
            float u1 = fmaxf(fmaf(px, wpa[c+1], fmaf(py, wpb[c+1], bpsh[c+1])), 0.f);
            Uhi[r*68 + j] = pack_hi(u0, u1);
            Ulo[r*68 + j] = pack_lo(u0, u1);
        }
        __syncthreads();

        // warp GEMM: m32 x n32 x k128, merged 3-term
        float acc[2][4][4];
        #pragma unroll
        for (int ms = 0; ms < 2; ms++)
            #pragma unroll
            for (int nt = 0; nt < 4; nt++)
                #pragma unroll
                for (int e = 0; e < 4; e++) acc[ms][nt][e] = 0.f;

        #pragma unroll
        for (int kt = 0; kt < 8; kt++) {
            const uint32_t ka = (uint32_t)(kt * 16) * 2u;
            uint32_t bh0[4], bl0[4], bh1[4], bl1[4];
            ldsm_x4(bh0, BhiA + boff0 + ka);
            ldsm_x4(bl0, BloA + boff0 + ka);
            ldsm_x4(bh1, BhiA + boff1 + ka);
            ldsm_x4(bl1, BloA + boff1 + ka);
            #pragma unroll
            for (int ms = 0; ms < 2; ms++) {
                const uint32_t ao = aoffb + (uint32_t)(ms * 16 * HS) * 2u + ka;
                uint32_t ah[4], al[4];
                ldsm_x4(ah, UhiA + ao);
                ldsm_x4(al, UloA + ao);
                #pragma unroll
                for (int sub = 0; sub < 2; sub++) {
                    mma16816(acc[ms][sub],   ah, bh0[sub], bh0[2+sub]);
                    mma16816(acc[ms][2+sub], ah, bh1[sub], bh1[2+sub]);
                    mma16816(acc[ms][sub],   ah, bl0[sub], bl0[2+sub]);
                    mma16816(acc[ms][2+sub], ah, bl1[sub], bl1[2+sub]);
                    mma16816(acc[ms][sub],   al, bh0[sub], bh0[2+sub]);
                    mma16816(acc[ms][2+sub], al, bh1[sub], bh1[2+sub]);
                }
            }
        }

        // fused epilogue: partial logits for 32 rows over this c-quarter
        #pragma unroll
        for (int ms = 0; ms < 2; ms++) {
            #pragma unroll
            for (int rh = 0; rh < 2; rh++) {
                int bl_ = m0 + ms*16 + rh*8 + (lane >> 2);       // 0..63 in chunk
                int bg  = chunk*64 + bl_;
                const float2* qp = (const float2*)(g_qW1 + (size_t)(n*PP + bg)*CC + qcol);
                float rp = 0.f;
                #pragma unroll
                for (int nt = 0; nt < 4; nt++) {
                    float2 q2 = __ldg(&qp[nt*4]);
                    int c = n0 + nt*8 + (lane & 3)*2;
                    float h0 = acc[ms][nt][rh*2 + 0] + q2.x + kcsh[c];
                    float h1 = acc[ms][nt][rh*2 + 1] + q2.y + kcsh[c + 1];
                    rp = fmaf(fmaxf(h0, 0.f), W2sh[c],
                         fmaf(fmaxf(h1, 0.f), W2sh[c + 1], rp));
                }
                rp += __shfl_xor_sync(0xffffffffu, rp, 1);
                rp += __shfl_xor_sync(0xffffffffu, rp, 2);
                if ((lane & 3) == 0) lp[ci][bl_] = rp;
            }
        }
        __syncthreads();

        // combine c-quarter partials for this chunk
        if (tid < 64)
            logits[chunk*64 + tid] = (lp[0][tid] + lp[1][tid]) + (lp[2][tid] + lp[3][tid]);
    }
    __syncthreads();

    // softmax over b (256 entries, 256 threads)
    float lv = logits[tid];
    red[tid] = lv;
    __syncthreads();
    #pragma unroll
    for (int s = 128; s > 0; s >>= 1) {
        if (tid < s) red[tid] = fmaxf(red[tid], red[tid + s]);
        __syncthreads();
    }
    float mx = red[0];
    __syncthreads();
    float ev = expf(lv - mx);
    red[tid] = ev;
    __syncthreads();
    #pragma unroll
    for (int s = 128; s > 0; s >>= 1) {
        if (tid < s) red[tid] += red[tid + s];
        __syncthreads();
    }
    float inv = 1.0f / red[0];
    __syncthreads();
    logits[tid] = ev * inv;
    __syncthreads();

    // out[n,a,:] = x[n,a,:] + att @ v[n]   (2-way split of the b-sum)
    {
        int d = tid & 127, h = tid >> 7;       // h in 0..1
        const float* vb = &g_v[(size_t)(n*PP + h*128)*CC + d];
        float s0 = 0.f, s1 = 0.f;
        #pragma unroll 4
        for (int b = 0; b < 128; b += 2) {
            s0 = fmaf(logits[h*128 + b    ], vb[(size_t)b*CC],     s0);
            s1 = fmaf(logits[h*128 + b + 1], vb[(size_t)(b+1)*CC], s1);
        }
        red[tid] = s0 + s1;
    }
    __syncthreads();
    if (tid < CC) {
        size_t o = (size_t)(n*PP + a)*CC + tid;
        out[o] = x[o] + red[tid] + red[tid + 128];
    }
}

// ---------------------------------------------------------------------------
extern "C" void kernel_launch(void* const* d_in, const int* in_sizes, int n_in,
                              void* d_out, int out_size) {
    const float* x   = (const float*)d_in[0];
    const float* pos = (const float*)d_in[1];
    const float* Wq  = (const float*)d_in[2];
    const float* Wk  = (const float*)d_in[3];
    const float* Wv  = (const float*)d_in[4];
    const float* W1  = (const float*)d_in[5];
    const float* b1  = (const float*)d_in[6];
    const float* W2  = (const float*)d_in[7];
    // d_in[8] = b2: cancelled by softmax
    const float* Wp1 = (const float*)d_in[9];
    const float* bp1 = (const float*)d_in[10];
    const float* Wp2 = (const float*)d_in[11];
    const float* bp2 = (const float*)d_in[12];
    float* out = (float*)d_out;

    const int smem_prep = (CC*CC + 16*CC) * 4;   // 73728
    const int smem_proj = (CC*CC + 64*US) * 4;   // 99328
    const int smem_main = 104448;                // B hi/lo + U-chunk hi/lo
    cudaFuncSetAttribute(prep1,       cudaFuncAttributeMaxDynamicSharedMemorySize, smem_prep);
    cudaFuncSetAttribute(proj_kernel, cudaFuncAttributeMaxDynamicSharedMemorySize, smem_proj);
    cudaFuncSetAttribute(main_kernel, cudaFuncAttributeMaxDynamicSharedMemorySize, smem_main);

    prep1<<<dim3(8, 3), 256, smem_prep>>>(Wq, Wk, Wp2, W1, b1, bp2);
    prep2<<<32, 256>>>();
    proj_kernel<<<dim3(NB*PP/64, 3), 256, smem_proj>>>(x, Wv);
    main_kernel<<<NB*PP, 256, smem_main>>>(x, pos, W2, Wp1, bp1, out);
}

// round 10
// speedup vs baseline: 1.5288x; 1.1921x over previous
#include <cuda_runtime.h>
#include <cuda_bf16.h>
#include <cstdint>

#define NB 8
#define PP 256
#define CC 128
#define US 132          // fp32 smem pad stride (proj kernel)
#define HS 136          // bf16 smem pad stride in halves (272B): conflict-free ldmatrix

// ---- scratch (no allocation allowed) --------------------------------------
__device__ __align__(16) float g_M[CC*CC];     // Wp2 @ W1
__device__ __align__(16) float g_Wq1[CC*CC];   // Wq @ W1
__device__ __align__(16) float g_Wk1[CC*CC];   // Wk @ W1
__device__ __align__(16) float g_c0[CC];       // b1 + bp2 @ W1
__device__ __align__(16) float g_v[NB*PP*CC];
__device__ __align__(16) float g_qW1[NB*PP*CC];
__device__ __align__(16) float g_kW1[NB*PP*CC];
// Mt (=M^T) split bf16 hi/lo, n-major rows: row d (out dim), 128 k cols, packed pairs
__device__ __align__(16) unsigned g_Bhi[CC*64];
__device__ __align__(16) unsigned g_Blo[CC*64];

// ---- helpers --------------------------------------------------------------
__device__ __forceinline__ uint32_t smem_u32(const void* p) {
    uint32_t r;
    asm("{ .reg .u64 t; cvta.to.shared.u64 t, %1; cvt.u32.u64 %0, t; }" : "=r"(r) : "l"(p));
    return r;
}
__device__ __forceinline__ void ldsm_x4(uint32_t* r, uint32_t addr) {
    asm volatile("ldmatrix.sync.aligned.m8n8.x4.shared.b16 {%0,%1,%2,%3}, [%4];"
                 : "=r"(r[0]), "=r"(r[1]), "=r"(r[2]), "=r"(r[3]) : "r"(addr));
}
__device__ __forceinline__ void mma16816(float* d, const uint32_t* a, uint32_t b0, uint32_t b1) {
    asm volatile("mma.sync.aligned.m16n8k16.row.col.f32.bf16.bf16.f32 "
                 "{%0,%1,%2,%3}, {%4,%5,%6,%7}, {%8,%9}, {%0,%1,%2,%3};"
                 : "+f"(d[0]), "+f"(d[1]), "+f"(d[2]), "+f"(d[3])
                 : "r"(a[0]), "r"(a[1]), "r"(a[2]), "r"(a[3]), "r"(b0), "r"(b1));
}
__device__ __forceinline__ unsigned pack_hi(float x, float y) {
    __nv_bfloat16 h0 = __float2bfloat16_rn(x), h1 = __float2bfloat16_rn(y);
    return ((unsigned)__bfloat16_as_ushort(h1) << 16) | __bfloat16_as_ushort(h0);
}
__device__ __forceinline__ unsigned pack_lo(float x, float y) {
    __nv_bfloat16 h0 = __float2bfloat16_rn(x), h1 = __float2bfloat16_rn(y);
    __nv_bfloat16 l0 = __float2bfloat16_rn(x - __bfloat162float(h0));
    __nv_bfloat16 l1 = __float2bfloat16_rn(y - __bfloat162float(h1));
    return ((unsigned)__bfloat16_as_ushort(l1) << 16) | __bfloat16_as_ushort(l0);
}

// ---------------------------------------------------------------------------
// prep1: parallel weight-fold GEMMs (M, Wq1, Wk1, c0). grid (8,3), W1 in smem.
// ---------------------------------------------------------------------------
__global__ __launch_bounds__(256)
void prep1(const float* __restrict__ Wq, const float* __restrict__ Wk,
           const float* __restrict__ Wp2, const float* __restrict__ W1,
           const float* __restrict__ b1, const float* __restrict__ bp2) {
    extern __shared__ float sm[];
    float* W1s = sm;           // 16384 floats
    float* Ash = sm + CC*CC;   // 16*128
    const float* A = (blockIdx.y == 0) ? Wp2 : ((blockIdx.y == 1) ? Wq : Wk);
    float* O       = (blockIdx.y == 0) ? g_M : ((blockIdx.y == 1) ? g_Wq1 : g_Wk1);
    int r0 = blockIdx.x * 16;
    int tid = threadIdx.x;
    for (int i = tid; i < CC*CC/4; i += 256) ((float4*)W1s)[i] = ((const float4*)W1)[i];
    for (int i = tid; i < 16*CC/4; i += 256) ((float4*)Ash)[i] = ((const float4*)(A + r0*CC))[i];
    __syncthreads();
    int d = tid & 127, r2 = tid >> 7;
    #pragma unroll
    for (int rr = 0; rr < 8; rr++) {
        int r = r2*8 + rr;
        float s = 0.f;
        #pragma unroll 8
        for (int e = 0; e < CC; e++) s = fmaf(Ash[r*CC + e], W1s[e*CC + d], s);
        O[(r0 + r)*CC + d] = s;
    }
    if (blockIdx.x == 0 && blockIdx.y == 0 && tid < CC) {
        float s = b1[tid];
        for (int e = 0; e < CC; e++) s = fmaf(bp2[e], W1s[e*CC + tid], s);
        g_c0[tid] = s;
    }
}

// ---------------------------------------------------------------------------
// prep2: build Mt (=M^T) bf16 hi/lo, plain n-major (row=d, 64 packed k-pairs)
// ---------------------------------------------------------------------------
__global__ void prep2() {
    int i = blockIdx.x * 256 + threadIdx.x;      // 0..8191
    int d = i >> 6, pc = i & 63, c = pc * 2;
    float m0 = g_M[c*CC + d], m1 = g_M[(c+1)*CC + d];   // Mt[d][c], Mt[d][c+1]
    g_Bhi[d*64 + pc] = pack_hi(m0, m1);
    g_Blo[d*64 + pc] = pack_lo(m0, m1);
}

// ---------------------------------------------------------------------------
// proj: v = x@Wv, qW1 = x@Wq1, kW1 = x@Wk1  (fp32 SIMT)
// ---------------------------------------------------------------------------
__global__ __launch_bounds__(256, 2)
void proj_kernel(const float* __restrict__ x, const float* __restrict__ Wv) {
    extern __shared__ float sm[];
    float* Wsh = sm;
    float* Xsh = sm + CC*CC;
    int which = blockIdx.y;
    const float* W = (which == 0) ? Wv  : ((which == 1) ? g_Wq1 : g_Wk1);
    float*       O = (which == 0) ? g_v : ((which == 1) ? g_qW1 : g_kW1);
    int row0 = blockIdx.x * 64;
    int tid = threadIdx.x;
    for (int i = tid; i < CC*CC/4; i += 256) ((float4*)Wsh)[i] = ((const float4*)W)[i];
    for (int i = tid; i < 64*CC; i += 256) {
        int r = i >> 7, c = i & 127;
        Xsh[r*US + c] = x[(row0 + r)*CC + c];
    }
    __syncthreads();
    int tx = tid & 15, ty = tid >> 4;
    float acc[4][8];
    #pragma unroll
    for (int i = 0; i < 4; i++)
        #pragma unroll
        for (int j = 0; j < 8; j++) acc[i][j] = 0.f;
    #pragma unroll 4
    for (int c = 0; c < CC; c++) {
        float4 m0 = *(const float4*)&Wsh[c*CC + (tx << 3)];
        float4 m1 = *(const float4*)&Wsh[c*CC + (tx << 3) + 4];
        float m[8] = {m0.x, m0.y, m0.z, m0.w, m1.x, m1.y, m1.z, m1.w};
        float u[4];
        #pragma unroll
        for (int i = 0; i < 4; i++) u[i] = Xsh[(ty*4 + i)*US + c];
        #pragma unroll
        for (int i = 0; i < 4; i++)
            #pragma unroll
            for (int j = 0; j < 8; j++) acc[i][j] += u[i] * m[j];
    }
    #pragma unroll
    for (int i = 0; i < 4; i++) {
        float4* o4 = (float4*)&O[(row0 + ty*4 + i)*CC + (tx << 3)];
        o4[0] = make_float4(acc[i][0], acc[i][1], acc[i][2], acc[i][3]);
        o4[1] = make_float4(acc[i][4], acc[i][5], acc[i][6], acc[i][7]);
    }
}

// ---------------------------------------------------------------------------
// main: per (n,a) block, 256 threads / 8 warps, 2 blocks/SM. 2-TERM split:
// G = bf16(U)·(Bhi+Blo), fp32 accum (residual ~2^-9 rel, ~1e-4 on output).
// U built in 4 chunks of 64 rows (hi only). Warp = (mh, ci): m32 x n32 x k128.
// Shuffle-based softmax (3 barriers). att@v, residual.
// ---------------------------------------------------------------------------
__global__ __launch_bounds__(256, 2)
void main_kernel(const float* __restrict__ x, const float* __restrict__ pos,
                 const float* __restrict__ W2, const float* __restrict__ Wp1,
                 const float* __restrict__ bp1, float* __restrict__ out) {
    extern __shared__ __align__(16) char dyn[];
    __shared__ float kcsh[CC], W2sh[CC], wpa[CC], wpb[CC], bpsh[CC];
    __shared__ float logits[PP], red[PP], lp[4][64], pos_c[128], wred[16];

    const int blk = blockIdx.x;
    const int n = blk >> 8, a = blk & 255;
    const int tid = threadIdx.x;
    const int lane = tid & 31, w = tid >> 5;

    // dyn layout (bytes): Bhi 34816 | Blo 34816 | Uhi 17408 = 87040
    unsigned* Bhi = (unsigned*)dyn;
    unsigned* Blo = (unsigned*)(dyn + 34816);
    unsigned* Uhi = (unsigned*)(dyn + 69632);
    const uint32_t BhiA = smem_u32(dyn);
    const uint32_t BloA = BhiA + 34816;
    const uint32_t UhiA = BhiA + 69632;

    // stage small vectors + B tiles
    if (tid < CC) {
        kcsh[tid] = g_c0[tid] - g_kW1[(n*PP + a)*CC + tid];
        W2sh[tid] = W2[tid];
        wpa[tid]  = Wp1[tid];
        wpb[tid]  = Wp1[CC + tid];
        bpsh[tid] = bp1[tid];
    }
    for (int i = tid; i < CC*64; i += 256) {      // pad stride HS/2=68 uints
        int r = i >> 6, j = i & 63;
        Bhi[r*68 + j] = g_Bhi[i];
        Blo[r*68 + j] = g_Blo[i];
    }

    // warp roles
    const int ci = w & 3;          // c-quarter: cols [ci*32, +32)
    const int mh = w >> 2;         // m-half within 64-row chunk
    const int n0 = ci * 32;
    const int m0 = mh * 32;

    const int arow = ((lane >> 3) & 1) * 8 + (lane & 7);
    const int acol = (lane >> 4) * 8;
    const int brow = lane & 15;
    const int bcol = (lane >> 4) * 8;

    const uint32_t boff0 = (uint32_t)(((n0      + brow) * HS) + bcol) * 2u;
    const uint32_t boff1 = (uint32_t)(((n0 + 16 + brow) * HS) + bcol) * 2u;
    const uint32_t aoffb = (uint32_t)(((m0 + arow) * HS) + acol) * 2u;
    const int qcol = n0 + (lane & 3)*2;

    const float* posrow = pos + (size_t)((n*PP + a)*PP) * 2;

    #pragma unroll 1
    for (int chunk = 0; chunk < 4; chunk++) {
        if (tid < 128) pos_c[tid] = posrow[chunk*128 + tid];
        __syncthreads();

        // build U chunk = relu(pos@Wp1+bp1) -> bf16 hi only
        for (int i = tid; i < 64*64; i += 256) {
            int r = i >> 6, j = i & 63, c = j*2;
            float px = pos_c[r*2], py = pos_c[r*2 + 1];
            float u0 = fmaxf(fmaf(px, wpa[c],   fmaf(py, wpb[c],   bpsh[c]  )), 0.f);
            float u1 = fmaxf(fmaf(px, wpa[c+1], fmaf(py, wpb[c+1], bpsh[c+1])), 0.f);
            Uhi[r*68 + j] = pack_hi(u0, u1);
        }
        __syncthreads();

        // warp GEMM: m32 x n32 x k128, 2-term (U_hi x (B_hi + B_lo))
        float acc[2][4][4];
        #pragma unroll
        for (int ms = 0; ms < 2; ms++)
            #pragma unroll
            for (int nt = 0; nt < 4; nt++)
                #pragma unroll
                for (int e = 0; e < 4; e++) acc[ms][nt][e] = 0.f;

        #pragma unroll
        for (int kt = 0; kt < 8; kt++) {
            const uint32_t ka = (uint32_t)(kt * 16) * 2u;
            uint32_t bh0[4], bl0[4], bh1[4], bl1[4];
            ldsm_x4(bh0, BhiA + boff0 + ka);
            ldsm_x4(bl0, BloA + boff0 + ka);
            ldsm_x4(bh1, BhiA + boff1 + ka);
            ldsm_x4(bl1, BloA + boff1 + ka);
            #pragma unroll
            for (int ms = 0; ms < 2; ms++) {
                const uint32_t ao = aoffb + (uint32_t)(ms * 16 * HS) * 2u + ka;
                uint32_t ah[4];
                ldsm_x4(ah, UhiA + ao);
                #pragma unroll
                for (int sub = 0; sub < 2; sub++) {
                    mma16816(acc[ms][sub],   ah, bh0[sub], bh0[2+sub]);
                    mma16816(acc[ms][2+sub], ah, bh1[sub], bh1[2+sub]);
                    mma16816(acc[ms][sub],   ah, bl0[sub], bl0[2+sub]);
                    mma16816(acc[ms][2+sub], ah, bl1[sub], bl1[2+sub]);
                }
            }
        }

        // fused epilogue: partial logits for 32 rows over this c-quarter
        #pragma unroll
        for (int ms = 0; ms < 2; ms++) {
            #pragma unroll
            for (int rh = 0; rh < 2; rh++) {
                int bl_ = m0 + ms*16 + rh*8 + (lane >> 2);       // 0..63 in chunk
                int bg  = chunk*64 + bl_;
                const float2* qp = (const float2*)(g_qW1 + (size_t)(n*PP + bg)*CC + qcol);
                float rp = 0.f;
                #pragma unroll
                for (int nt = 0; nt < 4; nt++) {
                    float2 q2 = __ldg(&qp[nt*4]);
                    int c = n0 + nt*8 + (lane & 3)*2;
                    float h0 = acc[ms][nt][rh*2 + 0] + q2.x + kcsh[c];
                    float h1 = acc[ms][nt][rh*2 + 1] + q2.y + kcsh[c + 1];
                    rp = fmaf(fmaxf(h0, 0.f), W2sh[c],
                         fmaf(fmaxf(h1, 0.f), W2sh[c + 1], rp));
                }
                rp += __shfl_xor_sync(0xffffffffu, rp, 1);
                rp += __shfl_xor_sync(0xffffffffu, rp, 2);
                if ((lane & 3) == 0) lp[ci][bl_] = rp;
            }
        }
        __syncthreads();

        // combine c-quarter partials for this chunk
        if (tid < 64)
            logits[chunk*64 + tid] = (lp[0][tid] + lp[1][tid]) + (lp[2][tid] + lp[3][tid]);
    }
    __syncthreads();

    // softmax over b (256 entries) — shuffle-based, 3 barriers
    float lv = logits[tid];
    {
        float m = lv;
        #pragma unroll
        for (int o = 16; o > 0; o >>= 1) m = fmaxf(m, __shfl_xor_sync(0xffffffffu, m, o));
        if (lane == 0) wred[w] = m;
    }
    __syncthreads();
    float mx = wred[0];
    #pragma unroll
    for (int i = 1; i < 8; i++) mx = fmaxf(mx, wred[i]);
    float ev = expf(lv - mx);
    {
        float s = ev;
        #pragma unroll
        for (int o = 16; o > 0; o >>= 1) s += __shfl_xor_sync(0xffffffffu, s, o);
        if (lane == 0) wred[8 + w] = s;
    }
    __syncthreads();
    float sum = (wred[8] + wred[9]) + (wred[10] + wred[11])
              + (wred[12] + wred[13]) + (wred[14] + wred[15]);
    logits[tid] = ev * (1.0f / sum);
    __syncthreads();

    // out[n,a,:] = x[n,a,:] + att @ v[n]   (2-way split of the b-sum)
    {
        int d = tid & 127, h = tid >> 7;       // h in 0..1
        const float* vb = &g_v[(size_t)(n*PP + h*128)*CC + d];
        float s0 = 0.f, s1 = 0.f;
        #pragma unroll 4
        for (int b = 0; b < 128; b += 2) {
            s0 = fmaf(logits[h*128 + b    ], vb[(size_t)b*CC],     s0);
            s1 = fmaf(logits[h*128 + b + 1], vb[(size_t)(b+1)*CC], s1);
        }
        red[tid] = s0 + s1;
    }
    __syncthreads();
    if (tid < CC) {
        size_t o = (size_t)(n*PP + a)*CC + tid;
        out[o] = x[o] + red[tid] + red[tid + 128];
    }
}

// ---------------------------------------------------------------------------
extern "C" void kernel_launch(void* const* d_in, const int* in_sizes, int n_in,
                              void* d_out, int out_size) {
    const float* x   = (const float*)d_in[0];
    const float* pos = (const float*)d_in[1];
    const float* Wq  = (const float*)d_in[2];
    const float* Wk  = (const float*)d_in[3];
    const float* Wv  = (const float*)d_in[4];
    const float* W1  = (const float*)d_in[5];
    const float* b1  = (const float*)d_in[6];
    const float* W2  = (const float*)d_in[7];
    // d_in[8] = b2: cancelled by softmax
    const float* Wp1 = (const float*)d_in[9];
    const float* bp1 = (const float*)d_in[10];
    const float* Wp2 = (const float*)d_in[11];
    const float* bp2 = (const float*)d_in[12];
    float* out = (float*)d_out;

    const int smem_prep = (CC*CC + 16*CC) * 4;   // 73728
    const int smem_proj = (CC*CC + 64*US) * 4;   // 99328
    const int smem_main = 87040;                 // B hi/lo + U-chunk hi
    cudaFuncSetAttribute(prep1,       cudaFuncAttributeMaxDynamicSharedMemorySize, smem_prep);
    cudaFuncSetAttribute(proj_kernel, cudaFuncAttributeMaxDynamicSharedMemorySize, smem_proj);
    cudaFuncSetAttribute(main_kernel, cudaFuncAttributeMaxDynamicSharedMemorySize, smem_main);

    prep1<<<dim3(8, 3), 256, smem_prep>>>(Wq, Wk, Wp2, W1, b1, bp2);
    prep2<<<32, 256>>>();
    proj_kernel<<<dim3(NB*PP/64, 3), 256, smem_proj>>>(x, Wv);
    main_kernel<<<NB*PP, 256, smem_main>>>(x, pos, W2, Wp1, bp1, out);
}

// round 12
// speedup vs baseline: 1.8820x; 1.2310x over previous
#include <cuda_runtime.h>
#include <cuda_bf16.h>
#include <cuda_fp16.h>
#include <cstdint>

#define NB 8
#define PP 256
#define CC 128
#define US 132          // fp32 smem pad stride (proj kernel)
#define HS 136          // f16 smem pad stride in halves (272B): conflict-free ldmatrix

// ---- scratch (no allocation allowed) --------------------------------------
__device__ __align__(16) float g_M[CC*CC];     // Wp2 @ W1
__device__ __align__(16) float g_Wq1[CC*CC];   // Wq @ W1
__device__ __align__(16) float g_Wk1[CC*CC];   // Wk @ W1
__device__ __align__(16) float g_c0[CC];       // b1 + bp2 @ W1
__device__ __align__(16) float g_v[NB*PP*CC];
__device__ __align__(16) float g_qW1[NB*PP*CC];
__device__ __align__(16) float g_kW1[NB*PP*CC];
// Mt (=M^T) in fp16, n-major rows: row d (out dim), 128 k cols, packed half2
__device__ __align__(16) unsigned g_Bf[CC*64];

// ---- helpers --------------------------------------------------------------
__device__ __forceinline__ uint32_t smem_u32(const void* p) {
    uint32_t r;
    asm("{ .reg .u64 t; cvta.to.shared.u64 t, %1; cvt.u32.u64 %0, t; }" : "=r"(r) : "l"(p));
    return r;
}
__device__ __forceinline__ void ldsm_x4(uint32_t* r, uint32_t addr) {
    asm volatile("ldmatrix.sync.aligned.m8n8.x4.shared.b16 {%0,%1,%2,%3}, [%4];"
                 : "=r"(r[0]), "=r"(r[1]), "=r"(r[2]), "=r"(r[3]) : "r"(addr));
}
__device__ __forceinline__ void mma16816h(float* d, const uint32_t* a, uint32_t b0, uint32_t b1) {
    asm volatile("mma.sync.aligned.m16n8k16.row.col.f32.f16.f16.f32 "
                 "{%0,%1,%2,%3}, {%4,%5,%6,%7}, {%8,%9}, {%0,%1,%2,%3};"
                 : "+f"(d[0]), "+f"(d[1]), "+f"(d[2]), "+f"(d[3])
                 : "r"(a[0]), "r"(a[1]), "r"(a[2]), "r"(a[3]), "r"(b0), "r"(b1));
}
__device__ __forceinline__ unsigned pack_f16(float x, float y) {
    __half2 h = __floats2half2_rn(x, y);
    return *(unsigned*)&h;
}

// ---------------------------------------------------------------------------
// prep1: parallel weight-fold GEMMs (M, Wq1, Wk1, c0). grid (8,3), W1 in smem.
// ---------------------------------------------------------------------------
__global__ __launch_bounds__(256)
void prep1(const float* __restrict__ Wq, const float* __restrict__ Wk,
           const float* __restrict__ Wp2, const float* __restrict__ W1,
           const float* __restrict__ b1, const float* __restrict__ bp2) {
    extern __shared__ float sm[];
    float* W1s = sm;           // 16384 floats
    float* Ash = sm + CC*CC;   // 16*128
    const float* A = (blockIdx.y == 0) ? Wp2 : ((blockIdx.y == 1) ? Wq : Wk);
    float* O       = (blockIdx.y == 0) ? g_M : ((blockIdx.y == 1) ? g_Wq1 : g_Wk1);
    int r0 = blockIdx.x * 16;
    int tid = threadIdx.x;
    for (int i = tid; i < CC*CC/4; i += 256) ((float4*)W1s)[i] = ((const float4*)W1)[i];
    for (int i = tid; i < 16*CC/4; i += 256) ((float4*)Ash)[i] = ((const float4*)(A + r0*CC))[i];
    __syncthreads();
    int d = tid & 127, r2 = tid >> 7;
    #pragma unroll
    for (int rr = 0; rr < 8; rr++) {
        int r = r2*8 + rr;
        float s = 0.f;
        #pragma unroll 8
        for (int e = 0; e < CC; e++) s = fmaf(Ash[r*CC + e], W1s[e*CC + d], s);
        O[(r0 + r)*CC + d] = s;
    }
    if (blockIdx.x == 0 && blockIdx.y == 0 && tid < CC) {
        float s = b1[tid];
        for (int e = 0; e < CC; e++) s = fmaf(bp2[e], W1s[e*CC + tid], s);
        g_c0[tid] = s;
    }
}

// ---------------------------------------------------------------------------
// prep2: build Mt (=M^T) fp16, plain n-major (row=d, 64 packed k-pairs)
// ---------------------------------------------------------------------------
__global__ void prep2() {
    int i = blockIdx.x * 256 + threadIdx.x;      // 0..8191
    int d = i >> 6, pc = i & 63, c = pc * 2;
    g_Bf[d*64 + pc] = pack_f16(g_M[c*CC + d], g_M[(c+1)*CC + d]);
}

// ---------------------------------------------------------------------------
// proj: v = x@Wv, qW1 = x@Wq1, kW1 = x@Wk1  (fp32 SIMT)
// ---------------------------------------------------------------------------
__global__ __launch_bounds__(256, 2)
void proj_kernel(const float* __restrict__ x, const float* __restrict__ Wv) {
    extern __shared__ float sm[];
    float* Wsh = sm;
    float* Xsh = sm + CC*CC;
    int which = blockIdx.y;
    const float* W = (which == 0) ? Wv  : ((which == 1) ? g_Wq1 : g_Wk1);
    float*       O = (which == 0) ? g_v : ((which == 1) ? g_qW1 : g_kW1);
    int row0 = blockIdx.x * 64;
    int tid = threadIdx.x;
    for (int i = tid; i < CC*CC/4; i += 256) ((float4*)Wsh)[i] = ((const float4*)W)[i];
    for (int i = tid; i < 64*CC; i += 256) {
        int r = i >> 7, c = i & 127;
        Xsh[r*US + c] = x[(row0 + r)*CC + c];
    }
    __syncthreads();
    int tx = tid & 15, ty = tid >> 4;
    float acc[4][8];
    #pragma unroll
    for (int i = 0; i < 4; i++)
        #pragma unroll
        for (int j = 0; j < 8; j++) acc[i][j] = 0.f;
    #pragma unroll 4
    for (int c = 0; c < CC; c++) {
        float4 m0 = *(const float4*)&Wsh[c*CC + (tx << 3)];
        float4 m1 = *(const float4*)&Wsh[c*CC + (tx << 3) + 4];
        float m[8] = {m0.x, m0.y, m0.z, m0.w, m1.x, m1.y, m1.z, m1.w};
        float u[4];
        #pragma unroll
        for (int i = 0; i < 4; i++) u[i] = Xsh[(ty*4 + i)*US + c];
        #pragma unroll
        for (int i = 0; i < 4; i++)
            #pragma unroll
            for (int j = 0; j < 8; j++) acc[i][j] += u[i] * m[j];
    }
    #pragma unroll
    for (int i = 0; i < 4; i++) {
        float4* o4 = (float4*)&O[(row0 + ty*4 + i)*CC + (tx << 3)];
        o4[0] = make_float4(acc[i][0], acc[i][1], acc[i][2], acc[i][3]);
        o4[1] = make_float4(acc[i][4], acc[i][5], acc[i][6], acc[i][7]);
    }
}

// ---------------------------------------------------------------------------
// main: per (n,a) block, 256 threads / 8 warps, 3 blocks/SM. Single-term
// fp16 GEMM: G = f16(U) @ f16(Mt)^T, fp32 accum (rel err ~2^-11 per operand).
// U built in 4 chunks of 64 rows. Warp = (mh, ci): m32 x n32 x k128.
// Shuffle-based softmax. att@v, residual.
// ---------------------------------------------------------------------------
__global__ __launch_bounds__(256, 3)
void main_kernel(const float* __restrict__ x, const float* __restrict__ pos,
                 const float* __restrict__ W2, const float* __restrict__ Wp1,
                 const float* __restrict__ bp1, float* __restrict__ out) {
    extern __shared__ __align__(16) char dyn[];
    __shared__ float kcsh[CC], W2sh[CC], wpa[CC], wpb[CC], bpsh[CC];
    __shared__ float logits[PP], red[PP], lp[4][64], pos_c[128], wred[16];

    const int blk = blockIdx.x;
    const int n = blk >> 8, a = blk & 255;
    const int tid = threadIdx.x;
    const int lane = tid & 31, w = tid >> 5;

    // dyn layout (bytes): Bf 34816 | Uf 17408 = 52224
    unsigned* Bf = (unsigned*)dyn;
    unsigned* Uf = (unsigned*)(dyn + 34816);
    const uint32_t BfA = smem_u32(dyn);
    const uint32_t UfA = BfA + 34816;

    // stage small vectors + B tile
    if (tid < CC) {
        kcsh[tid] = g_c0[tid] - g_kW1[(n*PP + a)*CC + tid];
        W2sh[tid] = W2[tid];
        wpa[tid]  = Wp1[tid];
        wpb[tid]  = Wp1[CC + tid];
        bpsh[tid] = bp1[tid];
    }
    for (int i = tid; i < CC*64; i += 256) {      // pad stride HS/2=68 uints
        int r = i >> 6, j = i & 63;
        Bf[r*68 + j] = g_Bf[i];
    }

    // warp roles
    const int ci = w & 3;          // c-quarter: cols [ci*32, +32)
    const int mh = w >> 2;         // m-half within 64-row chunk
    const int n0 = ci * 32;
    const int m0 = mh * 32;

    const int arow = ((lane >> 3) & 1) * 8 + (lane & 7);
    const int acol = (lane >> 4) * 8;
    const int brow = lane & 15;
    const int bcol = (lane >> 4) * 8;

    const uint32_t boff0 = (uint32_t)(((n0      + brow) * HS) + bcol) * 2u;
    const uint32_t boff1 = (uint32_t)(((n0 + 16 + brow) * HS) + bcol) * 2u;
    const uint32_t aoffb = (uint32_t)(((m0 + arow) * HS) + acol) * 2u;
    const int qcol = n0 + (lane & 3)*2;

    const float* posrow = pos + (size_t)((n*PP + a)*PP) * 2;

    #pragma unroll 1
    for (int chunk = 0; chunk < 4; chunk++) {
        if (tid < 128) pos_c[tid] = posrow[chunk*128 + tid];
        __syncthreads();

        // build U chunk = relu(pos@Wp1+bp1) -> fp16
        for (int i = tid; i < 64*64; i += 256) {
            int r = i >> 6, j = i & 63, c = j*2;
            float px = pos_c[r*2], py = pos_c[r*2 + 1];
            float u0 = fmaxf(fmaf(px, wpa[c],   fmaf(py, wpb[c],   bpsh[c]  )), 0.f);
            float u1 = fmaxf(fmaf(px, wpa[c+1], fmaf(py, wpb[c+1], bpsh[c+1])), 0.f);
            Uf[r*68 + j] = pack_f16(u0, u1);
        }
        __syncthreads();

        // warp GEMM: m32 x n32 x k128, single-term fp16
        float acc[2][4][4];
        #pragma unroll
        for (int ms = 0; ms < 2; ms++)
            #pragma unroll
            for (int nt = 0; nt < 4; nt++)
                #pragma unroll
                for (int e = 0; e < 4; e++) acc[ms][nt][e] = 0.f;

        #pragma unroll
        for (int kt = 0; kt < 8; kt++) {
            const uint32_t ka = (uint32_t)(kt * 16) * 2u;
            uint32_t b0[4], b1[4];
            ldsm_x4(b0, BfA + boff0 + ka);
            ldsm_x4(b1, BfA + boff1 + ka);
            #pragma unroll
            for (int ms = 0; ms < 2; ms++) {
                const uint32_t ao = aoffb + (uint32_t)(ms * 16 * HS) * 2u + ka;
                uint32_t ah[4];
                ldsm_x4(ah, UfA + ao);
                #pragma unroll
                for (int sub = 0; sub < 2; sub++) {
                    mma16816h(acc[ms][sub],   ah, b0[sub], b0[2+sub]);
                    mma16816h(acc[ms][2+sub], ah, b1[sub], b1[2+sub]);
                }
            }
        }

        // fused epilogue: partial logits for 32 rows over this c-quarter
        #pragma unroll
        for (int ms = 0; ms < 2; ms++) {
            #pragma unroll
            for (int rh = 0; rh < 2; rh++) {
                int bl_ = m0 + ms*16 + rh*8 + (lane >> 2);       // 0..63 in chunk
                int bg  = chunk*64 + bl_;
                const float2* qp = (const float2*)(g_qW1 + (size_t)(n*PP + bg)*CC + qcol);
                float rp = 0.f;
                #pragma unroll
                for (int nt = 0; nt < 4; nt++) {
                    float2 q2 = __ldg(&qp[nt*4]);
                    int c = n0 + nt*8 + (lane & 3)*2;
                    float h0 = acc[ms][nt][rh*2 + 0] + q2.x + kcsh[c];
                    float h1 = acc[ms][nt][rh*2 + 1] + q2.y + kcsh[c + 1];
                    rp = fmaf(fmaxf(h0, 0.f), W2sh[c],
                         fmaf(fmaxf(h1, 0.f), W2sh[c + 1], rp));
                }
                rp += __shfl_xor_sync(0xffffffffu, rp, 1);
                rp += __shfl_xor_sync(0xffffffffu, rp, 2);
                if ((lane & 3) == 0) lp[ci][bl_] = rp;
            }
        }
        __syncthreads();

        // combine c-quarter partials for this chunk
        if (tid < 64)
            logits[chunk*64 + tid] = (lp[0][tid] + lp[1][tid]) + (lp[2][tid] + lp[3][tid]);
    }
    __syncthreads();

    // softmax over b (256 entries) — shuffle-based
    float lv = logits[tid];
    {
        float m = lv;
        #pragma unroll
        for (int o = 16; o > 0; o >>= 1) m = fmaxf(m, __shfl_xor_sync(0xffffffffu, m, o));
        if (lane == 0) wred[w] = m;
    }
    __syncthreads();
    float mx = wred[0];
    #pragma unroll
    for (int i = 1; i < 8; i++) mx = fmaxf(mx, wred[i]);
    float ev = expf(lv - mx);
    {
        float s = ev;
        #pragma unroll
        for (int o = 16; o > 0; o >>= 1) s += __shfl_xor_sync(0xffffffffu, s, o);
        if (lane == 0) wred[8 + w] = s;
    }
    __syncthreads();
    float sum = (wred[8] + wred[9]) + (wred[10] + wred[11])
              + (wred[12] + wred[13]) + (wred[14] + wred[15]);
    logits[tid] = ev * (1.0f / sum);
    __syncthreads();

    // out[n,a,:] = x[n,a,:] + att @ v[n]   (2-way split of the b-sum)
    {
        int d = tid & 127, h = tid >> 7;       // h in 0..1
        const float* vb = &g_v[(size_t)(n*PP + h*128)*CC + d];
        float s0 = 0.f, s1 = 0.f;
        #pragma unroll 4
        for (int b = 0; b < 128; b += 2) {
            s0 = fmaf(logits[h*128 + b    ], vb[(size_t)b*CC],     s0);
            s1 = fmaf(logits[h*128 + b + 1], vb[(size_t)(b+1)*CC], s1);
        }
        red[tid] = s0 + s1;
    }
    __syncthreads();
    if (tid < CC) {
        size_t o = (size_t)(n*PP + a)*CC + tid;
        out[o] = x[o] + red[tid] + red[tid + 128];
    }
}

// ---------------------------------------------------------------------------
extern "C" void kernel_launch(void* const* d_in, const int* in_sizes, int n_in,
                              void* d_out, int out_size) {
    const float* x   = (const float*)d_in[0];
    const float* pos = (const float*)d_in[1];
    const float* Wq  = (const float*)d_in[2];
    const float* Wk  = (const float*)d_in[3];
    const float* Wv  = (const float*)d_in[4];
    const float* W1  = (const float*)d_in[5];
    const float* b1  = (const float*)d_in[6];
    const float* W2  = (const float*)d_in[7];
    // d_in[8] = b2: cancelled by softmax
    const float* Wp1 = (const float*)d_in[9];
    const float* bp1 = (const float*)d_in[10];
    const float* Wp2 = (const float*)d_in[11];
    const float* bp2 = (const float*)d_in[12];
    float* out = (float*)d_out;

    const int smem_prep = (CC*CC + 16*CC) * 4;   // 73728
    const int smem_proj = (CC*CC + 64*US) * 4;   // 99328
    const int smem_main = 52224;                 // Bf + U-chunk (fp16)
    cudaFuncSetAttribute(prep1,       cudaFuncAttributeMaxDynamicSharedMemorySize, smem_prep);
    cudaFuncSetAttribute(proj_kernel, cudaFuncAttributeMaxDynamicSharedMemorySize, smem_proj);
    cudaFuncSetAttribute(main_kernel, cudaFuncAttributeMaxDynamicSharedMemorySize, smem_main);

    prep1<<<dim3(8, 3), 256, smem_prep>>>(Wq, Wk, Wp2, W1, b1, bp2);
    prep2<<<32, 256>>>();
    proj_kernel<<<dim3(NB*PP/64, 3), 256, smem_proj>>>(x, Wv);
    main_kernel<<<NB*PP, 256, smem_main>>>(x, pos, W2, Wp1, bp1, out);
}

// round 13
// speedup vs baseline: 1.9379x; 1.0297x over previous
#include <cuda_runtime.h>
#include <cuda_bf16.h>
#include <cuda_fp16.h>
#include <cstdint>

#define NB 8
#define PP 256
#define CC 128
#define US 132          // fp32 smem pad stride (proj kernel)
#define HS 136          // f16 smem pad stride in halves (272B): conflict-free ldmatrix

// ---- scratch (no allocation allowed) --------------------------------------
__device__ __align__(16) float g_M[CC*CC];     // Wp2 @ W1
__device__ __align__(16) float g_Wq1[CC*CC];   // Wq @ W1
__device__ __align__(16) float g_Wk1[CC*CC];   // Wk @ W1
__device__ __align__(16) float g_c0[CC];       // b1 + bp2 @ W1
__device__ __align__(16) float g_v[NB*PP*CC];
__device__ __align__(16) float g_qW1[NB*PP*CC];
__device__ __align__(16) float g_kW1[NB*PP*CC];
// Mt (=M^T) in fp16, n-major rows: row d (out dim), 128 k cols, packed half2
__device__ __align__(16) unsigned g_Bf[CC*64];

// ---- helpers --------------------------------------------------------------
__device__ __forceinline__ uint32_t smem_u32(const void* p) {
    uint32_t r;
    asm("{ .reg .u64 t; cvta.to.shared.u64 t, %1; cvt.u32.u64 %0, t; }" : "=r"(r) : "l"(p));
    return r;
}
__device__ __forceinline__ void ldsm_x4(uint32_t* r, uint32_t addr) {
    asm volatile("ldmatrix.sync.aligned.m8n8.x4.shared.b16 {%0,%1,%2,%3}, [%4];"
                 : "=r"(r[0]), "=r"(r[1]), "=r"(r[2]), "=r"(r[3]) : "r"(addr));
}
__device__ __forceinline__ void mma16816h(float* d, const uint32_t* a, uint32_t b0, uint32_t b1) {
    asm volatile("mma.sync.aligned.m16n8k16.row.col.f32.f16.f16.f32 "
                 "{%0,%1,%2,%3}, {%4,%5,%6,%7}, {%8,%9}, {%0,%1,%2,%3};"
                 : "+f"(d[0]), "+f"(d[1]), "+f"(d[2]), "+f"(d[3])
                 : "r"(a[0]), "r"(a[1]), "r"(a[2]), "r"(a[3]), "r"(b0), "r"(b1));
}
__device__ __forceinline__ unsigned pack_f16(float x, float y) {
    __half2 h = __floats2half2_rn(x, y);
    return *(unsigned*)&h;
}

// ---------------------------------------------------------------------------
// prep1: parallel weight-fold GEMMs (M, Wq1, Wk1, c0). grid (8,3), W1 in smem.
// ---------------------------------------------------------------------------
__global__ __launch_bounds__(256)
void prep1(const float* __restrict__ Wq, const float* __restrict__ Wk,
           const float* __restrict__ Wp2, const float* __restrict__ W1,
           const float* __restrict__ b1, const float* __restrict__ bp2) {
    extern __shared__ float sm[];
    float* W1s = sm;           // 16384 floats
    float* Ash = sm + CC*CC;   // 16*128
    const float* A = (blockIdx.y == 0) ? Wp2 : ((blockIdx.y == 1) ? Wq : Wk);
    float* O       = (blockIdx.y == 0) ? g_M : ((blockIdx.y == 1) ? g_Wq1 : g_Wk1);
    int r0 = blockIdx.x * 16;
    int tid = threadIdx.x;
    for (int i = tid; i < CC*CC/4; i += 256) ((float4*)W1s)[i] = ((const float4*)W1)[i];
    for (int i = tid; i < 16*CC/4; i += 256) ((float4*)Ash)[i] = ((const float4*)(A + r0*CC))[i];
    __syncthreads();
    int d = tid & 127, r2 = tid >> 7;
    #pragma unroll
    for (int rr = 0; rr < 8; rr++) {
        int r = r2*8 + rr;
        float s = 0.f;
        #pragma unroll 8
        for (int e = 0; e < CC; e++) s = fmaf(Ash[r*CC + e], W1s[e*CC + d], s);
        O[(r0 + r)*CC + d] = s;
    }
    if (blockIdx.x == 0 && blockIdx.y == 0 && tid < CC) {
        float s = b1[tid];
        for (int e = 0; e < CC; e++) s = fmaf(bp2[e], W1s[e*CC + tid], s);
        g_c0[tid] = s;
    }
}

// ---------------------------------------------------------------------------
// prep2: build Mt (=M^T) fp16, plain n-major (row=d, 64 packed k-pairs)
// ---------------------------------------------------------------------------
__global__ void prep2() {
    int i = blockIdx.x * 256 + threadIdx.x;      // 0..8191
    int d = i >> 6, pc = i & 63, c = pc * 2;
    g_Bf[d*64 + pc] = pack_f16(g_M[c*CC + d], g_M[(c+1)*CC + d]);
}

// ---------------------------------------------------------------------------
// proj: v = x@Wv, qW1 = x@Wq1, kW1 = x@Wk1  (fp32 SIMT)
// ---------------------------------------------------------------------------
__global__ __launch_bounds__(256, 2)
void proj_kernel(const float* __restrict__ x, const float* __restrict__ Wv) {
    extern __shared__ float sm[];
    float* Wsh = sm;
    float* Xsh = sm + CC*CC;
    int which = blockIdx.y;
    const float* W = (which == 0) ? Wv  : ((which == 1) ? g_Wq1 : g_Wk1);
    float*       O = (which == 0) ? g_v : ((which == 1) ? g_qW1 : g_kW1);
    int row0 = blockIdx.x * 64;
    int tid = threadIdx.x;
    for (int i = tid; i < CC*CC/4; i += 256) ((float4*)Wsh)[i] = ((const float4*)W)[i];
    for (int i = tid; i < 64*CC; i += 256) {
        int r = i >> 7, c = i & 127;
        Xsh[r*US + c] = x[(row0 + r)*CC + c];
    }
    __syncthreads();
    int tx = tid & 15, ty = tid >> 4;
    float acc[4][8];
    #pragma unroll
    for (int i = 0; i < 4; i++)
        #pragma unroll
        for (int j = 0; j < 8; j++) acc[i][j] = 0.f;
    #pragma unroll 4
    for (int c = 0; c < CC; c++) {
        float4 m0 = *(const float4*)&Wsh[c*CC + (tx << 3)];
        float4 m1 = *(const float4*)&Wsh[c*CC + (tx << 3) + 4];
        float m[8] = {m0.x, m0.y, m0.z, m0.w, m1.x, m1.y, m1.z, m1.w};
        float u[4];
        #pragma unroll
        for (int i = 0; i < 4; i++) u[i] = Xsh[(ty*4 + i)*US + c];
        #pragma unroll
        for (int i = 0; i < 4; i++)
            #pragma unroll
            for (int j = 0; j < 8; j++) acc[i][j] += u[i] * m[j];
    }
    #pragma unroll
    for (int i = 0; i < 4; i++) {
        float4* o4 = (float4*)&O[(row0 + ty*4 + i)*CC + (tx << 3)];
        o4[0] = make_float4(acc[i][0], acc[i][1], acc[i][2], acc[i][3]);
        o4[1] = make_float4(acc[i][4], acc[i][5], acc[i][6], acc[i][7]);
    }
}

// ---------------------------------------------------------------------------
// main: per (n,a) block, 256 threads / 8 warps, 3 blocks/SM. Single-term
// fp16 GEMM: G = f16(U) @ f16(Mt)^T, fp32 accum. U built in 4 chunks of 64
// rows with per-thread HOISTED Wp1/bp1 registers (column fixed per thread).
// Warp = (mh, ci): m32 x n32 x k128. Shuffle softmax. att@v, residual.
// ---------------------------------------------------------------------------
__global__ __launch_bounds__(256, 3)
void main_kernel(const float* __restrict__ x, const float* __restrict__ pos,
                 const float* __restrict__ W2, const float* __restrict__ Wp1,
                 const float* __restrict__ bp1, float* __restrict__ out) {
    extern __shared__ __align__(16) char dyn[];
    __shared__ float kcsh[CC], W2sh[CC], wpa[CC], wpb[CC], bpsh[CC];
    __shared__ float logits[PP], red[PP], lp[4][64], pos_c[128], wred[16];

    const int blk = blockIdx.x;
    const int n = blk >> 8, a = blk & 255;
    const int tid = threadIdx.x;
    const int lane = tid & 31, w = tid >> 5;

    // dyn layout (bytes): Bf 34816 | Uf 17408 = 52224
    unsigned* Bf = (unsigned*)dyn;
    unsigned* Uf = (unsigned*)(dyn + 34816);
    const uint32_t BfA = smem_u32(dyn);
    const uint32_t UfA = BfA + 34816;

    // stage small vectors + B tile
    if (tid < CC) {
        kcsh[tid] = g_c0[tid] - g_kW1[(n*PP + a)*CC + tid];
        W2sh[tid] = W2[tid];
        wpa[tid]  = Wp1[tid];
        wpb[tid]  = Wp1[CC + tid];
        bpsh[tid] = bp1[tid];
    }
    for (int i = tid; i < CC*16; i += 256) {      // Bf staging, uint4 (pad 68)
        int r = i >> 4, j = i & 15;
        ((uint4*)(Bf + r*68))[j] = ((const uint4*)(g_Bf + r*64))[j];
    }
    __syncthreads();

    // hoisted per-thread U-build constants: column pair fixed (tid mod 64)
    const int jcol = tid & 63;
    const int c2 = jcol * 2;
    const int rbase = tid >> 6;          // 0..3
    const float wa0 = wpa[c2], wa1 = wpa[c2+1];
    const float wb0 = wpb[c2], wb1 = wpb[c2+1];
    const float bb0 = bpsh[c2], bb1 = bpsh[c2+1];

    // warp roles
    const int ci = w & 3;          // c-quarter: cols [ci*32, +32)
    const int mh = w >> 2;         // m-half within 64-row chunk
    const int n0 = ci * 32;
    const int m0 = mh * 32;

    const int arow = ((lane >> 3) & 1) * 8 + (lane & 7);
    const int acol = (lane >> 4) * 8;
    const int brow = lane & 15;
    const int bcol = (lane >> 4) * 8;

    const uint32_t boff0 = (uint32_t)(((n0      + brow) * HS) + bcol) * 2u;
    const uint32_t boff1 = (uint32_t)(((n0 + 16 + brow) * HS) + bcol) * 2u;
    const uint32_t aoffb = (uint32_t)(((m0 + arow) * HS) + acol) * 2u;
    const int qcol = n0 + (lane & 3)*2;

    const float* posrow = pos + (size_t)((n*PP + a)*PP) * 2;

    #pragma unroll 1
    for (int chunk = 0; chunk < 4; chunk++) {
        if (tid < 128) pos_c[tid] = posrow[chunk*128 + tid];
        __syncthreads();

        // build U chunk: 1 float2 LDS + 1 STS per 2 elements (consts hoisted)
        #pragma unroll
        for (int k = 0; k < 16; k++) {
            int r = rbase + k*4;
            float2 p = *(const float2*)&pos_c[r*2];
            float u0 = fmaxf(fmaf(p.x, wa0, fmaf(p.y, wb0, bb0)), 0.f);
            float u1 = fmaxf(fmaf(p.x, wa1, fmaf(p.y, wb1, bb1)), 0.f);
            Uf[r*68 + jcol] = pack_f16(u0, u1);
        }
        __syncthreads();

        // warp GEMM: m32 x n32 x k128, single-term fp16
        float acc[2][4][4];
        #pragma unroll
        for (int ms = 0; ms < 2; ms++)
            #pragma unroll
            for (int nt = 0; nt < 4; nt++)
                #pragma unroll
                for (int e = 0; e < 4; e++) acc[ms][nt][e] = 0.f;

        #pragma unroll
        for (int kt = 0; kt < 8; kt++) {
            const uint32_t ka = (uint32_t)(kt * 16) * 2u;
            uint32_t b0[4], b1[4];
            ldsm_x4(b0, BfA + boff0 + ka);
            ldsm_x4(b1, BfA + boff1 + ka);
            #pragma unroll
            for (int ms = 0; ms < 2; ms++) {
                const uint32_t ao = aoffb + (uint32_t)(ms * 16 * HS) * 2u + ka;
                uint32_t ah[4];
                ldsm_x4(ah, UfA + ao);
                #pragma unroll
                for (int sub = 0; sub < 2; sub++) {
                    mma16816h(acc[ms][sub],   ah, b0[sub], b0[2+sub]);
                    mma16816h(acc[ms][2+sub], ah, b1[sub], b1[2+sub]);
                }
            }
        }

        // fused epilogue: partial logits for 32 rows over this c-quarter
        #pragma unroll
        for (int ms = 0; ms < 2; ms++) {
            #pragma unroll
            for (int rh = 0; rh < 2; rh++) {
                int bl_ = m0 + ms*16 + rh*8 + (lane >> 2);       // 0..63 in chunk
                int bg  = chunk*64 + bl_;
                const float2* qp = (const float2*)(g_qW1 + (size_t)(n*PP + bg)*CC + qcol);
                float rp = 0.f;
                #pragma unroll
                for (int nt = 0; nt < 4; nt++) {
                    float2 q2 = __ldg(&qp[nt*4]);
                    int c = n0 + nt*8 + (lane & 3)*2;
                    float h0 = acc[ms][nt][rh*2 + 0] + q2.x + kcsh[c];
                    float h1 = acc[ms][nt][rh*2 + 1] + q2.y + kcsh[c + 1];
                    rp = fmaf(fmaxf(h0, 0.f), W2sh[c],
                         fmaf(fmaxf(h1, 0.f), W2sh[c + 1], rp));
                }
                rp += __shfl_xor_sync(0xffffffffu, rp, 1);
                rp += __shfl_xor_sync(0xffffffffu, rp, 2);
                if ((lane & 3) == 0) lp[ci][bl_] = rp;
            }
        }
        __syncthreads();

        // combine c-quarter partials for this chunk
        if (tid < 64)
            logits[chunk*64 + tid] = (lp[0][tid] + lp[1][tid]) + (lp[2][tid] + lp[3][tid]);
    }
    __syncthreads();

    // softmax over b (256 entries) — shuffle-based
    float lv = logits[tid];
    {
        float m = lv;
        #pragma unroll
        for (int o = 16; o > 0; o >>= 1) m = fmaxf(m, __shfl_xor_sync(0xffffffffu, m, o));
        if (lane == 0) wred[w] = m;
    }
    __syncthreads();
    float mx = wred[0];
    #pragma unroll
    for (int i = 1; i < 8; i++) mx = fmaxf(mx, wred[i]);
    float ev = expf(lv - mx);
    {
        float s = ev;
        #pragma unroll
        for (int o = 16; o > 0; o >>= 1) s += __shfl_xor_sync(0xffffffffu, s, o);
        if (lane == 0) wred[8 + w] = s;
    }
    __syncthreads();
    float sum = (wred[8] + wred[9]) + (wred[10] + wred[11])
              + (wred[12] + wred[13]) + (wred[14] + wred[15]);
    logits[tid] = ev * (1.0f / sum);
    __syncthreads();

    // out[n,a,:] = x[n,a,:] + att @ v[n]   (2-way split of the b-sum)
    {
        int d = tid & 127, h = tid >> 7;       // h in 0..1
        const float* vb = &g_v[(size_t)(n*PP + h*128)*CC + d];
        float s0 = 0.f, s1 = 0.f;
        #pragma unroll 4
        for (int b = 0; b < 128; b += 2) {
            s0 = fmaf(logits[h*128 + b    ], vb[(size_t)b*CC],     s0);
            s1 = fmaf(logits[h*128 + b + 1], vb[(size_t)(b+1)*CC], s1);
        }
        red[tid] = s0 + s1;
    }
    __syncthreads();
    if (tid < CC) {
        size_t o = (size_t)(n*PP + a)*CC + tid;
        out[o] = x[o] + red[tid] + red[tid + 128];
    }
}

// ---------------------------------------------------------------------------
extern "C" void kernel_launch(void* const* d_in, const int* in_sizes, int n_in,
                              void* d_out, int out_size) {
    const float* x   = (const float*)d_in[0];
    const float* pos = (const float*)d_in[1];
    const float* Wq  = (const float*)d_in[2];
    const float* Wk  = (const float*)d_in[3];
    const float* Wv  = (const float*)d_in[4];
    const float* W1  = (const float*)d_in[5];
    const float* b1  = (const float*)d_in[6];
    const float* W2  = (const float*)d_in[7];
    // d_in[8] = b2: cancelled by softmax
    const float* Wp1 = (const float*)d_in[9];
    const float* bp1 = (const float*)d_in[10];
    const float* Wp2 = (const float*)d_in[11];
    const float* bp2 = (const float*)d_in[12];
    float* out = (float*)d_out;

    const int smem_prep = (CC*CC + 16*CC) * 4;   // 73728
    const int smem_proj = (CC*CC + 64*US) * 4;   // 99328
    const int smem_main = 52224;                 // Bf + U-chunk (fp16)
    cudaFuncSetAttribute(prep1,       cudaFuncAttributeMaxDynamicSharedMemorySize, smem_prep);
    cudaFuncSetAttribute(proj_kernel, cudaFuncAttributeMaxDynamicSharedMemorySize, smem_proj);
    cudaFuncSetAttribute(main_kernel, cudaFuncAttributeMaxDynamicSharedMemorySize, smem_main);

    prep1<<<dim3(8, 3), 256, smem_prep>>>(Wq, Wk, Wp2, W1, b1, bp2);
    prep2<<<32, 256>>>();
    proj_kernel<<<dim3(NB*PP/64, 3), 256, smem_proj>>>(x, Wv);
    main_kernel<<<NB*PP, 256, smem_main>>>(x, pos, W2, Wp1, bp1, out);
}